// round 4
// baseline (speedup 1.0000x reference)
#include <cuda_runtime.h>

#define B_ 128
#define L_ 196
#define F_ 2048
#define H_ 512
#define A_ 512
#define M_TOTAL (B_*L_)   // 25088

#define TM 64
#define TN 128
#define TK 16

// Scratch (no cudaMalloc allowed)
__device__ float g_dec[B_*A_];        // [B, A] decoder context
__device__ float g_scores[M_TOTAL];   // [B*L] pre-softmax scores
__device__ float g_alpha[B_*L_];      // fallback alpha buffer

// ---------------------------------------------------------------------------
// Kernel 1: dec[b,a] = hidden[b,:] . W_dec[a,:] + b_dec[a]
// ---------------------------------------------------------------------------
__global__ void dec_kernel(const float* __restrict__ hidden,
                           const float* __restrict__ W_dec,
                           const float* __restrict__ b_dec) {
    __shared__ float h[H_];
    int b = blockIdx.x;
    int tid = threadIdx.x;
    for (int i = tid; i < H_; i += blockDim.x) h[i] = hidden[b*H_ + i];
    __syncthreads();
    for (int a = tid; a < A_; a += blockDim.x) {
        const float4* w = reinterpret_cast<const float4*>(W_dec + (size_t)a*H_);
        float s = b_dec[a];
        #pragma unroll 8
        for (int k = 0; k < H_/4; k++) {
            float4 wv = w[k];
            const float* hp = &h[k*4];
            s += wv.x*hp[0] + wv.y*hp[1] + wv.z*hp[2] + wv.w*hp[3];
        }
        g_dec[b*A_ + a] = s;
    }
}

// ---------------------------------------------------------------------------
// Kernel 2: fused enc-GEMM + relu + W_com reduction -> scores[b*L+l]
//   enc[m, a] = features[m,:] . W_enc[a,:]   (m = b*L + l)
//   scores[m] = sum_a relu(enc + b_enc[a] + dec[b,a]) * W_com[a] + b_com
// Tile: M=64 rows x N=128 cols, K-chunks of 16, 4 A-chunks serial in-CTA.
// ---------------------------------------------------------------------------
__global__ __launch_bounds__(256, 2)
void score_kernel(const float* __restrict__ features,
                  const float* __restrict__ W_enc,
                  const float* __restrict__ b_enc,
                  const float* __restrict__ W_com,
                  const float* __restrict__ b_com) {
    __shared__ float As[TK][TM + 4];   // transposed A tile [k][m], padded
    __shared__ float Bs[TK][TN + 4];   // transposed B tile [k][n], padded
    __shared__ float s_scores[TM];

    int tid = threadIdx.x;
    int tx = tid & 15;        // N direction (16)
    int ty = tid >> 4;        // M direction (16)
    int m0 = blockIdx.x * TM;

    if (tid < TM) s_scores[tid] = 0.f;

    // global->shared load mapping
    int lm  = tid >> 2;           // 0..63 : A-tile row
    int lk4 = (tid & 3) * 4;      // k offset (float4) for A
    int ln  = tid >> 1;           // 0..127: B-tile col (a index)
    int lk8 = (tid & 1) * 8;      // k offset (2x float4) for B

    float acc[4][8];

    for (int ac = 0; ac < 4; ac++) {
        int a0 = ac * TN;
        #pragma unroll
        for (int i = 0; i < 4; i++)
            #pragma unroll
            for (int j = 0; j < 8; j++) acc[i][j] = 0.f;

        for (int k0 = 0; k0 < F_; k0 += TK) {
            __syncthreads();
            // load A tile (features rows m0..m0+63, k0..k0+15)
            float4 av = *reinterpret_cast<const float4*>(
                features + (size_t)(m0 + lm)*F_ + k0 + lk4);
            As[lk4+0][lm] = av.x; As[lk4+1][lm] = av.y;
            As[lk4+2][lm] = av.z; As[lk4+3][lm] = av.w;
            // load B tile (W_enc rows a0..a0+127, k0..k0+15)
            const float* wrow = W_enc + (size_t)(a0 + ln)*F_ + k0 + lk8;
            float4 bv0 = *reinterpret_cast<const float4*>(wrow);
            float4 bv1 = *reinterpret_cast<const float4*>(wrow + 4);
            Bs[lk8+0][ln] = bv0.x; Bs[lk8+1][ln] = bv0.y;
            Bs[lk8+2][ln] = bv0.z; Bs[lk8+3][ln] = bv0.w;
            Bs[lk8+4][ln] = bv1.x; Bs[lk8+5][ln] = bv1.y;
            Bs[lk8+6][ln] = bv1.z; Bs[lk8+7][ln] = bv1.w;
            __syncthreads();

            #pragma unroll
            for (int k = 0; k < TK; k++) {
                float4 a  = *reinterpret_cast<const float4*>(&As[k][ty*4]);
                float4 b0 = *reinterpret_cast<const float4*>(&Bs[k][tx*4]);
                float4 b1 = *reinterpret_cast<const float4*>(&Bs[k][64 + tx*4]);
                float am[4] = {a.x, a.y, a.z, a.w};
                float bn[8] = {b0.x, b0.y, b0.z, b0.w, b1.x, b1.y, b1.z, b1.w};
                #pragma unroll
                for (int i = 0; i < 4; i++)
                    #pragma unroll
                    for (int j = 0; j < 8; j++)
                        acc[i][j] += am[i] * bn[j];
            }
        }

        // fused epilogue: relu(enc + b_enc + dec) * W_com, reduce over cols
        #pragma unroll
        for (int i = 0; i < 4; i++) {
            int row  = m0 + ty*4 + i;      // global m = b*L + l
            int bidx = row / L_;
            const float* decrow = g_dec + bidx*A_;
            float s = 0.f;
            #pragma unroll
            for (int j = 0; j < 8; j++) {
                int col = a0 + ((j < 4) ? (tx*4 + j) : (64 + tx*4 + j - 4));
                float e = acc[i][j] + b_enc[col] + decrow[col];
                s += fmaxf(e, 0.f) * W_com[col];
            }
            // reduce across the 16 tx lanes (each 16-lane half of the warp)
            #pragma unroll
            for (int off = 8; off >= 1; off >>= 1)
                s += __shfl_xor_sync(0xffffffffu, s, off);
            if (tx == 0) s_scores[ty*4 + i] += s;
        }
    }
    __syncthreads();
    if (tid < TM) g_scores[m0 + tid] = s_scores[tid] + b_com[0];
}

// ---------------------------------------------------------------------------
// Kernel 3: softmax over L per batch -> alpha
// ---------------------------------------------------------------------------
__global__ void softmax_kernel(float* __restrict__ alpha_out) {
    __shared__ float red[8];
    int b = blockIdx.x;
    int tid = threadIdx.x;
    int lane = tid & 31, warp = tid >> 5;

    float v = (tid < L_) ? g_scores[b*L_ + tid] : -3.0e38f;
    float m = v;
    #pragma unroll
    for (int off = 16; off; off >>= 1)
        m = fmaxf(m, __shfl_xor_sync(0xffffffffu, m, off));
    if (lane == 0) red[warp] = m;
    __syncthreads();
    if (tid == 0) {
        float t = red[0];
        #pragma unroll
        for (int i = 1; i < 8; i++) t = fmaxf(t, red[i]);
        red[0] = t;
    }
    __syncthreads();
    m = red[0];

    float e = (tid < L_) ? expf(v - m) : 0.f;
    float s = e;
    #pragma unroll
    for (int off = 16; off; off >>= 1)
        s += __shfl_xor_sync(0xffffffffu, s, off);
    __syncthreads();   // everyone has read red[0] before reuse
    if (lane == 0) red[warp] = s;
    __syncthreads();
    if (tid == 0) {
        float t = 0.f;
        #pragma unroll
        for (int i = 0; i < 8; i++) t += red[i];
        red[0] = t;
    }
    __syncthreads();
    float inv = 1.f / red[0];
    if (tid < L_) alpha_out[b*L_ + tid] = e * inv;
}

// ---------------------------------------------------------------------------
// Kernel 4: weighted_features[b,f] = sum_l features[b,l,f] * alpha[b,l]
// grid (F/512, B), 256 threads, 2 floats/thread
// ---------------------------------------------------------------------------
__global__ void weighted_kernel(const float* __restrict__ features,
                                const float* __restrict__ alpha,
                                float* __restrict__ out) {
    __shared__ float al[L_];
    int b  = blockIdx.y;
    int f  = blockIdx.x * 512 + threadIdx.x * 2;
    int tid = threadIdx.x;
    for (int i = tid; i < L_; i += 256) al[i] = alpha[b*L_ + i];
    __syncthreads();

    float2 acc = make_float2(0.f, 0.f);
    const float* base = features + (size_t)b*L_*F_ + f;
    #pragma unroll 4
    for (int l = 0; l < L_; l++) {
        float2 v = *reinterpret_cast<const float2*>(base + (size_t)l*F_);
        float a = al[l];
        acc.x += v.x * a;
        acc.y += v.y * a;
    }
    *reinterpret_cast<float2*>(out + (size_t)b*F_ + f) = acc;
}

// ---------------------------------------------------------------------------
extern "C" void kernel_launch(void* const* d_in, const int* in_sizes, int n_in,
                              void* d_out, int out_size) {
    const float* features = (const float*)d_in[0];
    const float* hidden   = (const float*)d_in[1];
    const float* W_enc    = (const float*)d_in[2];
    const float* b_enc    = (const float*)d_in[3];
    const float* W_dec    = (const float*)d_in[4];
    const float* b_dec    = (const float*)d_in[5];
    const float* W_com    = (const float*)d_in[6];
    const float* b_com    = (const float*)d_in[7];
    float* out = (float*)d_out;

    float* wf_out = out;              // [B, F] weighted features
    float* alpha_out;
    if (out_size >= B_*F_ + B_*L_) {
        alpha_out = out + (size_t)B_*F_;  // [B, L] alpha appended
    } else {
        // output is only weighted_features; keep alpha in scratch
        float* dev_alpha;
        cudaGetSymbolAddress((void**)&dev_alpha, g_alpha);
        alpha_out = dev_alpha;
    }

    dec_kernel<<<B_, 256>>>(hidden, W_dec, b_dec);
    score_kernel<<<M_TOTAL/TM, 256>>>(features, W_enc, b_enc, W_com, b_com);
    softmax_kernel<<<B_, 256>>>(alpha_out);
    weighted_kernel<<<dim3(F_/512, B_), 256>>>(features, alpha_out, wf_out);
}